// round 15
// baseline (speedup 1.0000x reference)
#include <cuda_runtime.h>
#include <cuda_fp16.h>
#include <cstdint>

// ============================================================================
// NT-Xent loss, GB300 (sm_103a) -- HMMA symmetric-Gram, persistent CTAs.
// R15 = R12 epilogue + 64KB CTA (A 32K + single B 32K) -> 3 CTAs/SM.
// Next tile's A/B are prefetched (cp.async) into the SAME buffers right
// after the mainloop's last smem read, hiding the fill under the epilogue.
// ============================================================================

#define N_TOTAL 8192
#define HALF    4096
#define DIM     128
#define SQRT_T  1.6986435838080746f   // sqrt(2*log2(e))

#define GRID_GRAM 444                  // 148 SMs * 3 CTAs

__device__ __half g_znh[N_TOTAL * DIM];          // rows scaled by SQRT_T
__device__ float g_rowsum[N_TOTAL];
__device__ float g_exc[N_TOTAL];                 // 2log2e * dot units
__device__ float g_acc;
__device__ unsigned int g_cnt;

__device__ __forceinline__ uint32_t smem_to_u32(const void* p) {
    uint32_t a;
    asm("{ .reg .u64 t; cvta.to.shared.u64 t, %1; cvt.u32.u64 %0, t; }"
        : "=r"(a) : "l"(p));
    return a;
}
__device__ __forceinline__ float ex2_approx(float x) {
    float y;
    asm("ex2.approx.f32 %0, %1;" : "=f"(y) : "f"(x));
    return y;
}
__device__ __forceinline__ uint32_t ex2_h2(uint32_t x) {
    uint32_t r;
    asm("ex2.approx.f16x2 %0, %1;" : "=r"(r) : "r"(x));
    return r;
}
__device__ __forceinline__ uint32_t hadd2b(uint32_t a, uint32_t b) {
    uint32_t r;
    asm("add.f16x2 %0, %1, %2;" : "=r"(r) : "r"(a), "r"(b));
    return r;
}
__device__ __forceinline__ float2 unpack_h2(uint32_t v) {
    __half2 h = *reinterpret_cast<__half2*>(&v);
    return __half22float2(h);
}

// ============================================================================
// Kernel 1: normalize -> fp16 * SQRT_T (one warp per row)
// ============================================================================
__global__ void normalize_kernel(const float* __restrict__ zi,
                                 const float* __restrict__ zj) {
    int row  = blockIdx.x * 8 + (threadIdx.x >> 5);
    int lane = threadIdx.x & 31;
    const float* src = (row < HALF) ? (zi + (size_t)row * DIM)
                                    : (zj + (size_t)(row - HALF) * DIM);
    float4 v = reinterpret_cast<const float4*>(src)[lane];
    float ss = v.x * v.x + v.y * v.y + v.z * v.z + v.w * v.w;
    #pragma unroll
    for (int o = 16; o; o >>= 1) ss += __shfl_xor_sync(0xFFFFFFFFu, ss, o);
    float inv = SQRT_T / fmaxf(sqrtf(ss), 1e-8f);
    __half2* dst = reinterpret_cast<__half2*>(g_znh + (size_t)row * DIM + lane * 4);
    dst[0] = __floats2half2_rn(v.x * inv, v.y * inv);
    dst[1] = __floats2half2_rn(v.z * inv, v.w * inv);
    if (lane == 0) g_rowsum[row] = 0.0f;
    if (row == 0 && lane == 0) { g_acc = 0.0f; g_cnt = 0u; }
}

// ============================================================================
// Kernel 2: persistent symmetric Gram GEMM, 3 CTAs/SM, prefetch-under-epilogue
// smem: A 32KB | B 32KB = 64KB
// ============================================================================
#define SMEM_A   0
#define SMEM_B   32768
#define SMEM_TOT 65536

__device__ __forceinline__ uint32_t tile_off(int row, int chunk16) {
    return (uint32_t)(row * 256 + ((chunk16 ^ (row & 7)) << 4));
}

__device__ __forceinline__ void load_tile_async(uint32_t sdst, int row0, int tid) {
    const uint4* gp = reinterpret_cast<const uint4*>(g_znh + (size_t)row0 * DIM);
    #pragma unroll
    for (int it = 0; it < 8; it++) {
        int idx = tid + it * 256;
        int row = idx >> 4, ch = idx & 15;
        asm volatile("cp.async.cg.shared.global [%0], [%1], 16;"
            :: "r"(sdst + tile_off(row, ch)), "l"(gp + (row << 4) + ch));
    }
}
#define CP_COMMIT() asm volatile("cp.async.commit_group;" ::: "memory")
#define CP_WAIT0()  asm volatile("cp.async.wait_group 0;"  ::: "memory")

__global__ void __launch_bounds__(256, 3)
gram_kernel() {
    extern __shared__ char smem[];
    uint32_t sb = smem_to_u32(smem);
    const int tid  = threadIdx.x;
    const int wid  = tid >> 5;
    const int lane = tid & 31;
    const int bid  = blockIdx.x;

    // 2080 tiles over 444 CTAs: first 304 get 5, rest 4
    const int start = bid * 4 + (bid < 304 ? bid : 304);
    const int count = 4 + (bid < 304 ? 1 : 0);

    int mi = 0, rem = start, len = 64;
    while (rem >= len) { rem -= len; len--; mi++; }
    int ni = mi + rem;

    const int wm = (wid & 3) * 32;
    const int wn = (wid >> 2) * 64;
    const int l7 = lane & 7;
    const int g  = lane >> 3;

    load_tile_async(sb + SMEM_A, mi << 7, tid);
    load_tile_async(sb + SMEM_B, ni << 7, tid);
    CP_COMMIT();
    CP_WAIT0();
    __syncthreads();

    for (int i = 0; i < count; i++) {
        const int m0 = mi << 7, n0 = ni << 7;
        const bool diag = (mi == ni);
        const bool excf = (ni - mi == (HALF >> 7));
        const bool last = (i == count - 1);
        int mi_n = mi, ni_n = ni + 1;
        if (ni_n == 64) { mi_n = mi + 1; ni_n = mi_n; }

        // ---- MMA mainloop (fp16 accumulate) ----
        uint32_t acc[2][8][2];
        #pragma unroll
        for (int mt = 0; mt < 2; mt++)
            #pragma unroll
            for (int nt = 0; nt < 8; nt++) { acc[mt][nt][0] = 0u; acc[mt][nt][1] = 0u; }

        #pragma unroll
        for (int ks = 0; ks < 8; ks++) {
            uint32_t a[2][4];
            #pragma unroll
            for (int mt = 0; mt < 2; mt++) {
                int row = wm + mt * 16 + l7 + ((g & 1) << 3);
                uint32_t addr = sb + SMEM_A + tile_off(row, ks * 2 + (g >> 1));
                asm volatile(
                    "ldmatrix.sync.aligned.m8n8.x4.shared.b16 {%0,%1,%2,%3}, [%4];"
                    : "=r"(a[mt][0]), "=r"(a[mt][1]), "=r"(a[mt][2]), "=r"(a[mt][3])
                    : "r"(addr));
            }
            uint32_t b[8][2];
            #pragma unroll
            for (int nt2 = 0; nt2 < 4; nt2++) {
                int row = wn + nt2 * 16 + l7 + ((g >> 1) << 3);
                uint32_t addr = sb + SMEM_B + tile_off(row, ks * 2 + (g & 1));
                asm volatile(
                    "ldmatrix.sync.aligned.m8n8.x4.shared.b16 {%0,%1,%2,%3}, [%4];"
                    : "=r"(b[nt2 * 2][0]),     "=r"(b[nt2 * 2][1]),
                      "=r"(b[nt2 * 2 + 1][0]), "=r"(b[nt2 * 2 + 1][1])
                    : "r"(addr));
            }
            #pragma unroll
            for (int mt = 0; mt < 2; mt++)
                #pragma unroll
                for (int nt = 0; nt < 8; nt++)
                    asm volatile(
                        "mma.sync.aligned.m16n8k16.row.col.f16.f16.f16.f16 "
                        "{%0,%1}, {%2,%3,%4,%5}, {%6,%7}, {%0,%1};"
                        : "+r"(acc[mt][nt][0]), "+r"(acc[mt][nt][1])
                        : "r"(a[mt][0]), "r"(a[mt][1]), "r"(a[mt][2]), "r"(a[mt][3]),
                          "r"(b[nt][0]), "r"(b[nt][1]));
        }

        // ---- all smem reads done; prefetch next tile under the epilogue ----
        __syncthreads();
        if (!last) {
            if (mi_n != mi) load_tile_async(sb + SMEM_A, mi_n << 7, tid);
            load_tile_async(sb + SMEM_B, ni_n << 7, tid);
            CP_COMMIT();
        }

        // ---- exc extraction (2log2e*dot units); pos is the constant 2.0 ----
        if (excf) {
            #pragma unroll
            for (int mt = 0; mt < 2; mt++)
                #pragma unroll
                for (int nt = 0; nt < 8; nt++)
                    #pragma unroll
                    for (int q = 0; q < 4; q++) {
                        int r_loc = wm + mt * 16 + (lane >> 2) + ((q & 2) << 2);
                        int c_loc = wn + nt * 8 + ((lane & 3) << 1) + (q & 1);
                        if (r_loc == c_loc) {
                            __half2 h = *reinterpret_cast<__half2*>(&acc[mt][nt][q >> 1]);
                            float v = __half2float((q & 1) ? __high2half(h)
                                                           : __low2half(h));
                            g_exc[m0 + r_loc] = v;
                            g_exc[n0 + r_loc] = v;
                        }
                    }
        }

        // ---- f16x2 epilogue (registers + global atomics only) ----
        uint32_t rs01[2] = {0u, 0u}, rs23[2] = {0u, 0u};
        uint32_t csv[8] = {0u, 0u, 0u, 0u, 0u, 0u, 0u, 0u};

        #pragma unroll
        for (int mt = 0; mt < 2; mt++) {
            #pragma unroll
            for (int nt = 0; nt < 8; nt++) {
                uint32_t p01 = ex2_h2(acc[mt][nt][0]);
                uint32_t p23 = ex2_h2(acc[mt][nt][1]);
                rs01[mt] = hadd2b(rs01[mt], p01);
                rs23[mt] = hadd2b(rs23[mt], p23);
                csv[nt]  = hadd2b(csv[nt], hadd2b(p01, p23));
            }
        }

        #pragma unroll
        for (int mt = 0; mt < 2; mt++) {
            uint32_t u = rs01[mt], w = rs23[mt];
            u = hadd2b(u, __shfl_xor_sync(0xFFFFFFFFu, u, 1));
            u = hadd2b(u, __shfl_xor_sync(0xFFFFFFFFu, u, 2));
            w = hadd2b(w, __shfl_xor_sync(0xFFFFFFFFu, w, 1));
            w = hadd2b(w, __shfl_xor_sync(0xFFFFFFFFu, w, 2));
            if ((lane & 3) == 0) {
                int r = m0 + wm + mt * 16 + (lane >> 2);
                float2 f0 = unpack_h2(u);
                float2 f1 = unpack_h2(w);
                atomicAdd(&g_rowsum[r],     f0.x + f0.y);
                atomicAdd(&g_rowsum[r + 8], f1.x + f1.y);
            }
        }

        if (!diag) {
            #pragma unroll
            for (int nt = 0; nt < 8; nt++) {
                uint32_t u = csv[nt];
                u = hadd2b(u, __shfl_xor_sync(0xFFFFFFFFu, u, 4));
                u = hadd2b(u, __shfl_xor_sync(0xFFFFFFFFu, u, 8));
                u = hadd2b(u, __shfl_xor_sync(0xFFFFFFFFu, u, 16));
                if (lane < 4) {
                    float2 f = unpack_h2(u);
                    int cix = n0 + wn + nt * 8 + (lane << 1);
                    atomicAdd(&g_rowsum[cix],     f.x);
                    atomicAdd(&g_rowsum[cix + 1], f.y);
                }
            }
        }

        // ---- wait for prefetched tile ----
        if (!last) {
            CP_WAIT0();
            __syncthreads();
            mi = mi_n; ni = ni_n;
        }
    }
}

// ============================================================================
// Kernel 3: finalize -> scalar loss (32 CTAs, last block writes)
// pos == dot(zn,zn)/TEMP == 2.0 exactly in nats.
// ============================================================================
__global__ void finalize_kernel(float* __restrict__ out) {
    __shared__ float red[256];
    int r = blockIdx.x * 256 + threadIdx.x;
    float S = g_rowsum[r] - ex2_approx(g_exc[r]);
    float acc = logf(S) - 2.0f;
    red[threadIdx.x] = acc;
    __syncthreads();
    #pragma unroll
    for (int s = 128; s > 0; s >>= 1) {
        if (threadIdx.x < s) red[threadIdx.x] += red[threadIdx.x + s];
        __syncthreads();
    }
    if (threadIdx.x == 0) {
        atomicAdd(&g_acc, red[0]);
        __threadfence();
        unsigned done = atomicAdd(&g_cnt, 1u);
        if (done == gridDim.x - 1) {
            float total = atomicAdd(&g_acc, 0.0f);
            out[0] = total / (float)N_TOTAL;
        }
    }
}

// ============================================================================
// launch
// ============================================================================
extern "C" void kernel_launch(void* const* d_in, const int* in_sizes, int n_in,
                              void* d_out, int out_size) {
    (void)in_sizes; (void)n_in; (void)out_size;
    const float* zi = (const float*)d_in[0];
    const float* zj = (const float*)d_in[1];
    float* out = (float*)d_out;

    normalize_kernel<<<N_TOTAL / 8, 256>>>(zi, zj);

    cudaFuncSetAttribute(gram_kernel,
                         cudaFuncAttributeMaxDynamicSharedMemorySize, SMEM_TOT);
    gram_kernel<<<GRID_GRAM, 256, SMEM_TOT>>>();

    finalize_kernel<<<N_TOTAL / 256, 256>>>(out);
}

// round 16
// speedup vs baseline: 1.0009x; 1.0009x over previous
#include <cuda_runtime.h>
#include <cuda_fp16.h>
#include <cstdint>

// ============================================================================
// NT-Xent loss, GB300 (sm_103a) -- HMMA symmetric-Gram, persistent CTAs.
// R16 = R12 + A fragments register-resident across each tile row (fp16
// accumulators make them fit: acc 32 + afr 64 + B 8 + addr ~15 < 128 regs).
// Mainloop is B-LDSM -> MMA only; A-LDSM runs once per mi change.
// ============================================================================

#define N_TOTAL 8192
#define HALF    4096
#define DIM     128
#define SQRT_T  1.6986435838080746f   // sqrt(2*log2(e))

#define GRID_GRAM 296

__device__ __half g_znh[N_TOTAL * DIM];          // rows scaled by SQRT_T
__device__ float g_rowsum[N_TOTAL];
__device__ float g_exc[N_TOTAL];                 // 2log2e * dot units
__device__ float g_acc;
__device__ unsigned int g_cnt;

__device__ __forceinline__ uint32_t smem_to_u32(const void* p) {
    uint32_t a;
    asm("{ .reg .u64 t; cvta.to.shared.u64 t, %1; cvt.u32.u64 %0, t; }"
        : "=r"(a) : "l"(p));
    return a;
}
__device__ __forceinline__ float ex2_approx(float x) {
    float y;
    asm("ex2.approx.f32 %0, %1;" : "=f"(y) : "f"(x));
    return y;
}
__device__ __forceinline__ uint32_t ex2_h2(uint32_t x) {
    uint32_t r;
    asm("ex2.approx.f16x2 %0, %1;" : "=r"(r) : "r"(x));
    return r;
}
__device__ __forceinline__ uint32_t hadd2b(uint32_t a, uint32_t b) {
    uint32_t r;
    asm("add.f16x2 %0, %1, %2;" : "=r"(r) : "r"(a), "r"(b));
    return r;
}
__device__ __forceinline__ float2 unpack_h2(uint32_t v) {
    __half2 h = *reinterpret_cast<__half2*>(&v);
    return __half22float2(h);
}

// ============================================================================
// Kernel 1: normalize -> fp16 * SQRT_T (one warp per row)
// ============================================================================
__global__ void normalize_kernel(const float* __restrict__ zi,
                                 const float* __restrict__ zj) {
    int row  = blockIdx.x * 8 + (threadIdx.x >> 5);
    int lane = threadIdx.x & 31;
    const float* src = (row < HALF) ? (zi + (size_t)row * DIM)
                                    : (zj + (size_t)(row - HALF) * DIM);
    float4 v = reinterpret_cast<const float4*>(src)[lane];
    float ss = v.x * v.x + v.y * v.y + v.z * v.z + v.w * v.w;
    #pragma unroll
    for (int o = 16; o; o >>= 1) ss += __shfl_xor_sync(0xFFFFFFFFu, ss, o);
    float inv = SQRT_T / fmaxf(sqrtf(ss), 1e-8f);
    __half2* dst = reinterpret_cast<__half2*>(g_znh + (size_t)row * DIM + lane * 4);
    dst[0] = __floats2half2_rn(v.x * inv, v.y * inv);
    dst[1] = __floats2half2_rn(v.z * inv, v.w * inv);
    if (lane == 0) g_rowsum[row] = 0.0f;
    if (row == 0 && lane == 0) { g_acc = 0.0f; g_cnt = 0u; }
}

// ============================================================================
// Kernel 2: persistent symmetric Gram GEMM, A-in-registers per tile row
// smem: A 32KB | B0 32KB | B1 32KB
// ============================================================================
#define SMEM_A   0
#define SMEM_B0  32768
#define SMEM_TOT 98304

__device__ __forceinline__ uint32_t tile_off(int row, int chunk16) {
    return (uint32_t)(row * 256 + ((chunk16 ^ (row & 7)) << 4));
}

__device__ __forceinline__ void load_tile_async(uint32_t sdst, int row0, int tid) {
    const uint4* gp = reinterpret_cast<const uint4*>(g_znh + (size_t)row0 * DIM);
    #pragma unroll
    for (int it = 0; it < 8; it++) {
        int idx = tid + it * 256;
        int row = idx >> 4, ch = idx & 15;
        asm volatile("cp.async.cg.shared.global [%0], [%1], 16;"
            :: "r"(sdst + tile_off(row, ch)), "l"(gp + (row << 4) + ch));
    }
}
#define CP_COMMIT() asm volatile("cp.async.commit_group;" ::: "memory")
#define CP_WAIT0()  asm volatile("cp.async.wait_group 0;"  ::: "memory")

__global__ void __launch_bounds__(256, 2)
gram_kernel() {
    extern __shared__ char smem[];
    uint32_t sb = smem_to_u32(smem);
    const int tid  = threadIdx.x;
    const int wid  = tid >> 5;
    const int lane = tid & 31;
    const int bid  = blockIdx.x;

    const int start = bid * 7 + (bid < 8 ? bid : 8);
    const int count = (bid < 8) ? 8 : 7;

    int mi = 0, rem = start, len = 64;
    while (rem >= len) { rem -= len; len--; mi++; }
    int ni = mi + rem;

    const int wm = (wid & 3) * 32;
    const int wn = (wid >> 2) * 64;
    const int l7 = lane & 7;
    const int g  = lane >> 3;

    load_tile_async(sb + SMEM_A, mi << 7, tid);
    load_tile_async(sb + SMEM_B0, ni << 7, tid);
    CP_COMMIT();
    CP_WAIT0();
    __syncthreads();
    int cur = 0;
    bool need_a = true;

    // A fragments: [mt][ks][4] -- register resident across the tile row
    uint32_t afr[2][8][4];

    for (int i = 0; i < count; i++) {
        const int m0 = mi << 7, n0 = ni << 7;
        const bool diag = (mi == ni);
        const bool excf = (ni - mi == (HALF >> 7));
        const bool last = (i == count - 1);
        int mi_n = mi, ni_n = ni + 1;
        if (ni_n == 64) { mi_n = mi + 1; ni_n = mi_n; }
        const bool pf = !last && (mi_n == mi);
        if (pf) {
            load_tile_async(sb + SMEM_B0 + ((1 - cur) << 15), ni_n << 7, tid);
            CP_COMMIT();
        }
        const uint32_t bbase = sb + SMEM_B0 + (cur << 15);

        // ---- load A fragments once per tile row ----
        if (need_a) {
            #pragma unroll
            for (int mt = 0; mt < 2; mt++) {
                int row = wm + mt * 16 + l7 + ((g & 1) << 3);
                #pragma unroll
                for (int ks = 0; ks < 8; ks++) {
                    uint32_t addr = sb + SMEM_A + tile_off(row, ks * 2 + (g >> 1));
                    asm volatile(
                        "ldmatrix.sync.aligned.m8n8.x4.shared.b16 {%0,%1,%2,%3}, [%4];"
                        : "=r"(afr[mt][ks][0]), "=r"(afr[mt][ks][1]),
                          "=r"(afr[mt][ks][2]), "=r"(afr[mt][ks][3])
                        : "r"(addr));
                }
            }
            need_a = false;
        }

        // ---- MMA mainloop: B-LDSM -> MMA only ----
        uint32_t acc[2][8][2];
        #pragma unroll
        for (int mt = 0; mt < 2; mt++)
            #pragma unroll
            for (int nt = 0; nt < 8; nt++) { acc[mt][nt][0] = 0u; acc[mt][nt][1] = 0u; }

        #pragma unroll
        for (int ks = 0; ks < 8; ks++) {
            uint32_t b[8][2];
            #pragma unroll
            for (int nt2 = 0; nt2 < 4; nt2++) {
                int row = wn + nt2 * 16 + l7 + ((g >> 1) << 3);
                uint32_t addr = bbase + tile_off(row, ks * 2 + (g & 1));
                asm volatile(
                    "ldmatrix.sync.aligned.m8n8.x4.shared.b16 {%0,%1,%2,%3}, [%4];"
                    : "=r"(b[nt2 * 2][0]),     "=r"(b[nt2 * 2][1]),
                      "=r"(b[nt2 * 2 + 1][0]), "=r"(b[nt2 * 2 + 1][1])
                    : "r"(addr));
            }
            #pragma unroll
            for (int mt = 0; mt < 2; mt++)
                #pragma unroll
                for (int nt = 0; nt < 8; nt++)
                    asm volatile(
                        "mma.sync.aligned.m16n8k16.row.col.f16.f16.f16.f16 "
                        "{%0,%1}, {%2,%3,%4,%5}, {%6,%7}, {%0,%1};"
                        : "+r"(acc[mt][nt][0]), "+r"(acc[mt][nt][1])
                        : "r"(afr[mt][ks][0]), "r"(afr[mt][ks][1]),
                          "r"(afr[mt][ks][2]), "r"(afr[mt][ks][3]),
                          "r"(b[nt][0]), "r"(b[nt][1]));
        }

        // ---- exc extraction (2log2e*dot units); pos is the constant 2.0 ----
        if (excf) {
            #pragma unroll
            for (int mt = 0; mt < 2; mt++)
                #pragma unroll
                for (int nt = 0; nt < 8; nt++)
                    #pragma unroll
                    for (int q = 0; q < 4; q++) {
                        int r_loc = wm + mt * 16 + (lane >> 2) + ((q & 2) << 2);
                        int c_loc = wn + nt * 8 + ((lane & 3) << 1) + (q & 1);
                        if (r_loc == c_loc) {
                            __half2 h = *reinterpret_cast<__half2*>(&acc[mt][nt][q >> 1]);
                            float v = __half2float((q & 1) ? __high2half(h)
                                                           : __low2half(h));
                            g_exc[m0 + r_loc] = v;
                            g_exc[n0 + r_loc] = v;
                        }
                    }
        }

        // ---- f16x2 epilogue: ex2 straight on accumulator regs ----
        uint32_t rs01[2] = {0u, 0u}, rs23[2] = {0u, 0u};
        uint32_t csv[8] = {0u, 0u, 0u, 0u, 0u, 0u, 0u, 0u};

        #pragma unroll
        for (int mt = 0; mt < 2; mt++) {
            #pragma unroll
            for (int nt = 0; nt < 8; nt++) {
                uint32_t p01 = ex2_h2(acc[mt][nt][0]);
                uint32_t p23 = ex2_h2(acc[mt][nt][1]);
                rs01[mt] = hadd2b(rs01[mt], p01);
                rs23[mt] = hadd2b(rs23[mt], p23);
                csv[nt]  = hadd2b(csv[nt], hadd2b(p01, p23));
            }
        }

        #pragma unroll
        for (int mt = 0; mt < 2; mt++) {
            uint32_t u = rs01[mt], w = rs23[mt];
            u = hadd2b(u, __shfl_xor_sync(0xFFFFFFFFu, u, 1));
            u = hadd2b(u, __shfl_xor_sync(0xFFFFFFFFu, u, 2));
            w = hadd2b(w, __shfl_xor_sync(0xFFFFFFFFu, w, 1));
            w = hadd2b(w, __shfl_xor_sync(0xFFFFFFFFu, w, 2));
            if ((lane & 3) == 0) {
                int r = m0 + wm + mt * 16 + (lane >> 2);
                float2 f0 = unpack_h2(u);
                float2 f1 = unpack_h2(w);
                atomicAdd(&g_rowsum[r],     f0.x + f0.y);
                atomicAdd(&g_rowsum[r + 8], f1.x + f1.y);
            }
        }

        if (!diag) {
            #pragma unroll
            for (int nt = 0; nt < 8; nt++) {
                uint32_t u = csv[nt];
                u = hadd2b(u, __shfl_xor_sync(0xFFFFFFFFu, u, 4));
                u = hadd2b(u, __shfl_xor_sync(0xFFFFFFFFu, u, 8));
                u = hadd2b(u, __shfl_xor_sync(0xFFFFFFFFu, u, 16));
                if (lane < 4) {
                    float2 f = unpack_h2(u);
                    int cix = n0 + wn + nt * 8 + (lane << 1);
                    atomicAdd(&g_rowsum[cix],     f.x);
                    atomicAdd(&g_rowsum[cix + 1], f.y);
                }
            }
        }

        // ---- advance pipeline ----
        if (!last) {
            if (pf) {
                CP_WAIT0();
                __syncthreads();
                cur ^= 1;
            } else {
                __syncthreads();
                load_tile_async(sb + SMEM_A, mi_n << 7, tid);
                load_tile_async(sb + SMEM_B0 + (cur << 15), ni_n << 7, tid);
                CP_COMMIT();
                CP_WAIT0();
                __syncthreads();
                need_a = true;
            }
            mi = mi_n; ni = ni_n;
        }
    }
}

// ============================================================================
// Kernel 3: finalize -> scalar loss (32 CTAs, last block writes)
// pos == dot(zn,zn)/TEMP == 2.0 exactly in nats.
// ============================================================================
__global__ void finalize_kernel(float* __restrict__ out) {
    __shared__ float red[256];
    int r = blockIdx.x * 256 + threadIdx.x;
    float S = g_rowsum[r] - ex2_approx(g_exc[r]);
    float acc = logf(S) - 2.0f;
    red[threadIdx.x] = acc;
    __syncthreads();
    #pragma unroll
    for (int s = 128; s > 0; s >>= 1) {
        if (threadIdx.x < s) red[threadIdx.x] += red[threadIdx.x + s];
        __syncthreads();
    }
    if (threadIdx.x == 0) {
        atomicAdd(&g_acc, red[0]);
        __threadfence();
        unsigned done = atomicAdd(&g_cnt, 1u);
        if (done == gridDim.x - 1) {
            float total = atomicAdd(&g_acc, 0.0f);
            out[0] = total / (float)N_TOTAL;
        }
    }
}

// ============================================================================
// launch
// ============================================================================
extern "C" void kernel_launch(void* const* d_in, const int* in_sizes, int n_in,
                              void* d_out, int out_size) {
    (void)in_sizes; (void)n_in; (void)out_size;
    const float* zi = (const float*)d_in[0];
    const float* zj = (const float*)d_in[1];
    float* out = (float*)d_out;

    normalize_kernel<<<N_TOTAL / 8, 256>>>(zi, zj);

    cudaFuncSetAttribute(gram_kernel,
                         cudaFuncAttributeMaxDynamicSharedMemorySize, SMEM_TOT);
    gram_kernel<<<GRID_GRAM, 256, SMEM_TOT>>>();

    finalize_kernel<<<N_TOTAL / 256, 256>>>(out);
}

// round 17
// speedup vs baseline: 1.0072x; 1.0063x over previous
#include <cuda_runtime.h>
#include <cuda_fp16.h>
#include <cstdint>

// ============================================================================
// NT-Xent loss, GB300 (sm_103a) -- HMMA symmetric-Gram, persistent CTAs.
// R17 = R12 (unchanged mainloop/epilogue) + finalize fused into gram's tail:
// end-of-kernel grid arrive/spin (296 CTAs = exactly 2/SM, co-resident),
// then all CTAs finalize 28 rows each in parallel; last CTA writes out and
// resets counters for graph replay.
// ============================================================================

#define N_TOTAL 8192
#define HALF    4096
#define DIM     128
#define SQRT_T  1.6986435838080746f   // sqrt(2*log2(e))

#define GRID_GRAM 296
#define ROWS_PER_CTA 28                // 296*28 = 8288 >= 8192

__device__ __half g_znh[N_TOTAL * DIM];          // rows scaled by SQRT_T
__device__ float g_rowsum[N_TOTAL];
__device__ float g_exc[N_TOTAL];                 // 2log2e * dot units
__device__ float g_acc;
__device__ unsigned int g_cnt;                   // gram-done counter
__device__ unsigned int g_cnt2;                  // finalize-done counter

__device__ __forceinline__ uint32_t smem_to_u32(const void* p) {
    uint32_t a;
    asm("{ .reg .u64 t; cvta.to.shared.u64 t, %1; cvt.u32.u64 %0, t; }"
        : "=r"(a) : "l"(p));
    return a;
}
__device__ __forceinline__ float ex2_approx(float x) {
    float y;
    asm("ex2.approx.f32 %0, %1;" : "=f"(y) : "f"(x));
    return y;
}
__device__ __forceinline__ uint32_t ex2_h2(uint32_t x) {
    uint32_t r;
    asm("ex2.approx.f16x2 %0, %1;" : "=r"(r) : "r"(x));
    return r;
}
__device__ __forceinline__ uint32_t hadd2b(uint32_t a, uint32_t b) {
    uint32_t r;
    asm("add.f16x2 %0, %1, %2;" : "=r"(r) : "r"(a), "r"(b));
    return r;
}
__device__ __forceinline__ float2 unpack_h2(uint32_t v) {
    __half2 h = *reinterpret_cast<__half2*>(&v);
    return __half22float2(h);
}

// ============================================================================
// Kernel 1: normalize -> fp16 * SQRT_T (one warp per row) + zero counters
// ============================================================================
__global__ void normalize_kernel(const float* __restrict__ zi,
                                 const float* __restrict__ zj) {
    int row  = blockIdx.x * 8 + (threadIdx.x >> 5);
    int lane = threadIdx.x & 31;
    const float* src = (row < HALF) ? (zi + (size_t)row * DIM)
                                    : (zj + (size_t)(row - HALF) * DIM);
    float4 v = reinterpret_cast<const float4*>(src)[lane];
    float ss = v.x * v.x + v.y * v.y + v.z * v.z + v.w * v.w;
    #pragma unroll
    for (int o = 16; o; o >>= 1) ss += __shfl_xor_sync(0xFFFFFFFFu, ss, o);
    float inv = SQRT_T / fmaxf(sqrtf(ss), 1e-8f);
    __half2* dst = reinterpret_cast<__half2*>(g_znh + (size_t)row * DIM + lane * 4);
    dst[0] = __floats2half2_rn(v.x * inv, v.y * inv);
    dst[1] = __floats2half2_rn(v.z * inv, v.w * inv);
    if (lane == 0) g_rowsum[row] = 0.0f;
    if (row == 0 && lane == 0) { g_acc = 0.0f; g_cnt = 0u; g_cnt2 = 0u; }
}

// ============================================================================
// Kernel 2: persistent symmetric Gram GEMM (R12) + fused parallel finalize
// smem: A 32KB | B0 32KB | B1 32KB
// ============================================================================
#define SMEM_A   0
#define SMEM_B0  32768
#define SMEM_TOT 98304

__device__ __forceinline__ uint32_t tile_off(int row, int chunk16) {
    return (uint32_t)(row * 256 + ((chunk16 ^ (row & 7)) << 4));
}

__device__ __forceinline__ void load_tile_async(uint32_t sdst, int row0, int tid) {
    const uint4* gp = reinterpret_cast<const uint4*>(g_znh + (size_t)row0 * DIM);
    #pragma unroll
    for (int it = 0; it < 8; it++) {
        int idx = tid + it * 256;
        int row = idx >> 4, ch = idx & 15;
        asm volatile("cp.async.cg.shared.global [%0], [%1], 16;"
            :: "r"(sdst + tile_off(row, ch)), "l"(gp + (row << 4) + ch));
    }
}
#define CP_COMMIT() asm volatile("cp.async.commit_group;" ::: "memory")
#define CP_WAIT0()  asm volatile("cp.async.wait_group 0;"  ::: "memory")

__global__ void __launch_bounds__(256, 2)
gram_kernel(float* __restrict__ out) {
    extern __shared__ char smem[];
    uint32_t sb = smem_to_u32(smem);
    const int tid  = threadIdx.x;
    const int wid  = tid >> 5;
    const int lane = tid & 31;
    const int bid  = blockIdx.x;

    const int start = bid * 7 + (bid < 8 ? bid : 8);
    const int count = (bid < 8) ? 8 : 7;

    int mi = 0, rem = start, len = 64;
    while (rem >= len) { rem -= len; len--; mi++; }
    int ni = mi + rem;

    const int wm = (wid & 3) * 32;
    const int wn = (wid >> 2) * 64;
    const int l7 = lane & 7;
    const int g  = lane >> 3;

    load_tile_async(sb + SMEM_A, mi << 7, tid);
    load_tile_async(sb + SMEM_B0, ni << 7, tid);
    CP_COMMIT();
    CP_WAIT0();
    __syncthreads();
    int cur = 0;

    for (int i = 0; i < count; i++) {
        const int m0 = mi << 7, n0 = ni << 7;
        const bool diag = (mi == ni);
        const bool excf = (ni - mi == (HALF >> 7));
        const bool last = (i == count - 1);
        int mi_n = mi, ni_n = ni + 1;
        if (ni_n == 64) { mi_n = mi + 1; ni_n = mi_n; }
        const bool pf = !last && (mi_n == mi);
        if (pf) {
            load_tile_async(sb + SMEM_B0 + ((1 - cur) << 15), ni_n << 7, tid);
            CP_COMMIT();
        }
        const uint32_t bbase = sb + SMEM_B0 + (cur << 15);

        // ---- MMA mainloop (fp16 accumulate) ----
        uint32_t acc[2][8][2];
        #pragma unroll
        for (int mt = 0; mt < 2; mt++)
            #pragma unroll
            for (int nt = 0; nt < 8; nt++) { acc[mt][nt][0] = 0u; acc[mt][nt][1] = 0u; }

        #pragma unroll
        for (int ks = 0; ks < 8; ks++) {
            uint32_t a[2][4];
            #pragma unroll
            for (int mt = 0; mt < 2; mt++) {
                int row = wm + mt * 16 + l7 + ((g & 1) << 3);
                uint32_t addr = sb + SMEM_A + tile_off(row, ks * 2 + (g >> 1));
                asm volatile(
                    "ldmatrix.sync.aligned.m8n8.x4.shared.b16 {%0,%1,%2,%3}, [%4];"
                    : "=r"(a[mt][0]), "=r"(a[mt][1]), "=r"(a[mt][2]), "=r"(a[mt][3])
                    : "r"(addr));
            }
            uint32_t b[8][2];
            #pragma unroll
            for (int nt2 = 0; nt2 < 4; nt2++) {
                int row = wn + nt2 * 16 + l7 + ((g >> 1) << 3);
                uint32_t addr = bbase + tile_off(row, ks * 2 + (g & 1));
                asm volatile(
                    "ldmatrix.sync.aligned.m8n8.x4.shared.b16 {%0,%1,%2,%3}, [%4];"
                    : "=r"(b[nt2 * 2][0]),     "=r"(b[nt2 * 2][1]),
                      "=r"(b[nt2 * 2 + 1][0]), "=r"(b[nt2 * 2 + 1][1])
                    : "r"(addr));
            }
            #pragma unroll
            for (int mt = 0; mt < 2; mt++)
                #pragma unroll
                for (int nt = 0; nt < 8; nt++)
                    asm volatile(
                        "mma.sync.aligned.m16n8k16.row.col.f16.f16.f16.f16 "
                        "{%0,%1}, {%2,%3,%4,%5}, {%6,%7}, {%0,%1};"
                        : "+r"(acc[mt][nt][0]), "+r"(acc[mt][nt][1])
                        : "r"(a[mt][0]), "r"(a[mt][1]), "r"(a[mt][2]), "r"(a[mt][3]),
                          "r"(b[nt][0]), "r"(b[nt][1]));
        }

        // ---- exc extraction (2log2e*dot units); pos is the constant 2.0 ----
        if (excf) {
            #pragma unroll
            for (int mt = 0; mt < 2; mt++)
                #pragma unroll
                for (int nt = 0; nt < 8; nt++)
                    #pragma unroll
                    for (int q = 0; q < 4; q++) {
                        int r_loc = wm + mt * 16 + (lane >> 2) + ((q & 2) << 2);
                        int c_loc = wn + nt * 8 + ((lane & 3) << 1) + (q & 1);
                        if (r_loc == c_loc) {
                            __half2 h = *reinterpret_cast<__half2*>(&acc[mt][nt][q >> 1]);
                            float v = __half2float((q & 1) ? __high2half(h)
                                                           : __low2half(h));
                            g_exc[m0 + r_loc] = v;
                            g_exc[n0 + r_loc] = v;
                        }
                    }
        }

        // ---- f16x2 epilogue: ex2 straight on accumulator regs ----
        uint32_t rs01[2] = {0u, 0u}, rs23[2] = {0u, 0u};
        uint32_t csv[8] = {0u, 0u, 0u, 0u, 0u, 0u, 0u, 0u};

        #pragma unroll
        for (int mt = 0; mt < 2; mt++) {
            #pragma unroll
            for (int nt = 0; nt < 8; nt++) {
                uint32_t p01 = ex2_h2(acc[mt][nt][0]);
                uint32_t p23 = ex2_h2(acc[mt][nt][1]);
                rs01[mt] = hadd2b(rs01[mt], p01);
                rs23[mt] = hadd2b(rs23[mt], p23);
                csv[nt]  = hadd2b(csv[nt], hadd2b(p01, p23));
            }
        }

        #pragma unroll
        for (int mt = 0; mt < 2; mt++) {
            uint32_t u = rs01[mt], w = rs23[mt];
            u = hadd2b(u, __shfl_xor_sync(0xFFFFFFFFu, u, 1));
            u = hadd2b(u, __shfl_xor_sync(0xFFFFFFFFu, u, 2));
            w = hadd2b(w, __shfl_xor_sync(0xFFFFFFFFu, w, 1));
            w = hadd2b(w, __shfl_xor_sync(0xFFFFFFFFu, w, 2));
            if ((lane & 3) == 0) {
                int r = m0 + wm + mt * 16 + (lane >> 2);
                float2 f0 = unpack_h2(u);
                float2 f1 = unpack_h2(w);
                atomicAdd(&g_rowsum[r],     f0.x + f0.y);
                atomicAdd(&g_rowsum[r + 8], f1.x + f1.y);
            }
        }

        if (!diag) {
            #pragma unroll
            for (int nt = 0; nt < 8; nt++) {
                uint32_t u = csv[nt];
                u = hadd2b(u, __shfl_xor_sync(0xFFFFFFFFu, u, 4));
                u = hadd2b(u, __shfl_xor_sync(0xFFFFFFFFu, u, 8));
                u = hadd2b(u, __shfl_xor_sync(0xFFFFFFFFu, u, 16));
                if (lane < 4) {
                    float2 f = unpack_h2(u);
                    int cix = n0 + wn + nt * 8 + (lane << 1);
                    atomicAdd(&g_rowsum[cix],     f.x);
                    atomicAdd(&g_rowsum[cix + 1], f.y);
                }
            }
        }

        // ---- advance pipeline ----
        if (!last) {
            if (pf) {
                CP_WAIT0();
                __syncthreads();
                cur ^= 1;
            } else {
                __syncthreads();
                load_tile_async(sb + SMEM_A, mi_n << 7, tid);
                load_tile_async(sb + SMEM_B0 + (cur << 15), ni_n << 7, tid);
                CP_COMMIT();
                CP_WAIT0();
                __syncthreads();
            }
            mi = mi_n; ni = ni_n;
        }
    }

    // =================== fused finalize (end-of-kernel barrier) =============
    __syncthreads();
    __threadfence();
    if (tid == 0) {
        atomicAdd(&g_cnt, 1u);
        while (atomicAdd(&g_cnt, 0u) < GRID_GRAM) { }
    }
    __syncthreads();

    // each CTA finalizes ROWS_PER_CTA rows (warp 0 only; trivial work)
    if (wid == 0) {
        int r = bid * ROWS_PER_CTA + lane;
        float term = 0.0f;
        if (lane < ROWS_PER_CTA && r < N_TOTAL) {
            float S = atomicAdd(&g_rowsum[r], 0.0f) - ex2_approx(g_exc[r]);
            term = logf(S) - 2.0f;
        }
        #pragma unroll
        for (int o = 16; o; o >>= 1) term += __shfl_xor_sync(0xFFFFFFFFu, term, o);
        if (lane == 0) {
            atomicAdd(&g_acc, term);
            __threadfence();
            unsigned done = atomicAdd(&g_cnt2, 1u);
            if (done == GRID_GRAM - 1) {
                float total = atomicAdd(&g_acc, 0.0f);
                out[0] = total / (float)N_TOTAL;
                g_acc = 0.0f; g_cnt = 0u; g_cnt2 = 0u;
                __threadfence();
            }
        }
    }
}

// ============================================================================
// launch
// ============================================================================
extern "C" void kernel_launch(void* const* d_in, const int* in_sizes, int n_in,
                              void* d_out, int out_size) {
    (void)in_sizes; (void)n_in; (void)out_size;
    const float* zi = (const float*)d_in[0];
    const float* zj = (const float*)d_in[1];
    float* out = (float*)d_out;

    normalize_kernel<<<N_TOTAL / 8, 256>>>(zi, zj);

    cudaFuncSetAttribute(gram_kernel,
                         cudaFuncAttributeMaxDynamicSharedMemorySize, SMEM_TOT);
    gram_kernel<<<GRID_GRAM, 256, SMEM_TOT>>>(out);
}